// round 14
// baseline (speedup 1.0000x reference)
#include <cuda_runtime.h>
#include <cuda_fp16.h>
#include <cstdint>

// ---------------- problem constants ----------------
#define N_INPUT   1024
#define N_OUTPUT  512
#define BATCHC    32
#define T_STEPS   100
#define TB_LEN    100                    // per-b t-length (no padding)
#define K_DIM     (BATCHC * TB_LEN)      // 3200
#define K_SPLIT   2
#define K_PART    (K_DIM / K_SPLIT)      // 1600
#define CHUNK     64                     // k per pipeline stage
#define NCHUNKS   (K_PART / CHUNK)       // 25

#define DECAY     (0.951229424500714f)   // exp(-1/20)
#define D26       (0.272531793034013f)   // exp(-26/20)

#define LR_LTP_F  (1e-4f)
#define LR_LTD_F  (-1e-4f)

#define PRETR_OFF  (N_OUTPUT * N_INPUT)
#define POSTTR_OFF (PRETR_OFF + BATCHC * N_INPUT)

// ---------------- device scratch (no allocations) ----------------
static __device__ __align__(16) __half g_A0[N_OUTPUT * K_DIM]; // postS  [o][k]
static __device__ __align__(16) __half g_A1[N_OUTPUT * K_DIM]; // postTr [o][k]
static __device__ __align__(16) __half g_B0[N_INPUT  * K_DIM]; // preTr  [i][k]
static __device__ __align__(16) __half g_B1[N_INPUT  * K_DIM]; // preS   [i][k]
static __device__ float g_P0[K_SPLIT * N_OUTPUT * N_INPUT];    // ltp partials
static __device__ float g_P1[K_SPLIT * N_OUTPUT * N_INPUT];    // ltd partials

// ---------------- helpers ----------------
__device__ __forceinline__ uint32_t smem_u32(const void* p) {
    uint32_t a;
    asm("{ .reg .u64 t; cvta.to.shared.u64 t, %1; cvt.u32.u64 %0, t; }"
        : "=r"(a) : "l"(p));
    return a;
}
__device__ __forceinline__ void cp_async16(uint32_t dst, const void* src) {
    asm volatile("cp.async.cg.shared.global [%0], [%1], 16;"
                 :: "r"(dst), "l"(src) : "memory");
}
#define CP_COMMIT() asm volatile("cp.async.commit_group;" ::: "memory")
#define CP_WAIT1()  asm volatile("cp.async.wait_group 1;" ::: "memory")

__device__ __forceinline__ void ldm_x4(uint32_t* r, uint32_t addr) {
    asm volatile("ldmatrix.sync.aligned.m8n8.x4.shared.b16 {%0,%1,%2,%3}, [%4];"
                 : "=r"(r[0]), "=r"(r[1]), "=r"(r[2]), "=r"(r[3]) : "r"(addr));
}
__device__ __forceinline__ void mma16816(float* c, const uint32_t* a,
                                         uint32_t b0, uint32_t b1) {
    asm volatile(
        "mma.sync.aligned.m16n8k16.row.col.f32.f16.f16.f32 "
        "{%0,%1,%2,%3}, {%4,%5,%6,%7}, {%8,%9}, {%0,%1,%2,%3};"
        : "+f"(c[0]), "+f"(c[1]), "+f"(c[2]), "+f"(c[3])
        : "r"(a[0]), "r"(a[1]), "r"(a[2]), "r"(a[3]), "r"(b0), "r"(b1));
}
__device__ __forceinline__ uint32_t pack_h2(float a, float b) {
    __half2 h = __halves2half2(__float2half(a), __float2half(b));
    return *(uint32_t*)&h;
}

// ===========================================================================
// Kernel 1: prep — segmented trace scan + fp16 K-major transpose.
// CTA = (b, 128 cols). Warp = (seg, 64 cols), lane owns 2 adjacent cols
// (float2 loads). Segments t0 = {0,26,52,78}, uniform L=26 (tail predicated,
// pads beyond t=99 never copied out). Pass 1 stages fp16 spikes in smem
// (0/1 -> lossless) and computes partial-scan end values; pass 2 recomputes
// the scan from smem with the carry E folded in (no pv register array).
// Grid: pre 32b x 8 grps = 256 CTAs + post 32b x 4 = 128 CTAs -> 384.
// ===========================================================================
__global__ void __launch_bounds__(256) prep_kernel(
    const float* __restrict__ pre_s,    // [100][32][1024]
    const float* __restrict__ post_s,   // [100][32][512]
    const float* __restrict__ pre_tr0,
    const float* __restrict__ post_tr0,
    float* __restrict__ out)
{
    __shared__ uint32_t s_sp[128][53];  // spike fp16 pairs; word w = t/2
    __shared__ uint32_t s_tr[128][53];  // trace fp16 pairs
    __shared__ float    s_P[3][128];    // partial-scan ends, segs 0..2

    const int bx = blockIdx.x, tid = threadIdx.x;
    const int w = tid >> 5, lane = tid & 31;
    const int seg = w >> 1;
    const int colL = (w & 1) * 64 + 2 * lane;       // even, 0..126

    const float *src, *tr0p;
    __half *trd, *spd;
    int b, col0, nc, outbase;
    if (bx < 256) {                                 // pre side
        b = bx >> 3; col0 = (bx & 7) * 128; nc = N_INPUT;
        src = pre_s; tr0p = pre_tr0; trd = g_B0; spd = g_B1;
        outbase = PRETR_OFF + b * N_INPUT;
    } else {                                        // post side
        int e = bx - 256;
        b = e >> 2; col0 = (e & 3) * 128; nc = N_OUTPUT;
        src = post_s; tr0p = post_tr0; trd = g_A1; spd = g_A0;
        outbase = POSTTR_OFF + b * N_OUTPUT;
    }
    const int col = col0 + colL;
    const int srcbase = b * nc + col;               // even
    const float2* src2 = (const float2*)src;
    const int s2 = srcbase >> 1;
    const int tslice2 = (BATCHC * nc) >> 1;         // float2 stride per t
    const int t0 = (seg < 3) ? seg * 26 : 78;

    // ---- pass 1: load spikes (float2), stage fp16, partial scan from 0
    float p0 = 0.f, p1 = 0.f;
    #pragma unroll
    for (int i = 0; i < 26; i += 2) {
        const int t = t0 + i;
        float2 va = (t     < T_STEPS) ? src2[(size_t)t       * tslice2 + s2]
                                      : make_float2(0.f, 0.f);
        float2 vb = (t + 1 < T_STEPS) ? src2[(size_t)(t + 1) * tslice2 + s2]
                                      : make_float2(0.f, 0.f);
        const int wi = (t0 + i) >> 1;
        s_sp[colL    ][wi] = pack_h2(va.x, vb.x);
        s_sp[colL + 1][wi] = pack_h2(va.y, vb.y);
        p0 = p0 * DECAY + va.x; p0 = p0 * DECAY + vb.x;
        p1 = p1 * DECAY + va.y; p1 = p1 * DECAY + vb.y;
    }
    if (seg < 3) { s_P[seg][colL] = p0; s_P[seg][colL + 1] = p1; }
    __syncthreads();

    // ---- carries: E = trace entering this segment
    float E0 = tr0p[srcbase], E1 = tr0p[srcbase + 1];
    if (seg > 0) { E0 = E0 * D26 + s_P[0][colL]; E1 = E1 * D26 + s_P[0][colL + 1]; }
    if (seg > 1) { E0 = E0 * D26 + s_P[1][colL]; E1 = E1 * D26 + s_P[1][colL + 1]; }
    if (seg > 2) { E0 = E0 * D26 + s_P[2][colL]; E1 = E1 * D26 + s_P[2][colL + 1]; }

    // ---- pass 2: recompute scan from smem spikes with carry folded in
    float r0 = E0, r1 = E1, fin0 = 0.f, fin1 = 0.f;
    #pragma unroll
    for (int i = 0; i < 26; i += 2) {
        const int wi = (t0 + i) >> 1;
        uint32_t u0 = s_sp[colL][wi], u1 = s_sp[colL + 1][wi];
        float2 f0 = __half22float2(*(__half2*)&u0);
        float2 f1 = __half22float2(*(__half2*)&u1);
        r0 = r0 * DECAY + f0.x; float a0 = r0; r0 = r0 * DECAY + f0.y;
        r1 = r1 * DECAY + f1.x; float a1 = r1; r1 = r1 * DECAY + f1.y;
        s_tr[colL    ][wi] = pack_h2(a0, r0);
        s_tr[colL + 1][wi] = pack_h2(a1, r1);
        if (t0 + i + 1 == 99) { fin0 = r0; fin1 = r1; }   // t = 99 (seg 3, i=20)
    }
    __syncthreads();

    // ---- coalesced copy-out: 128 rows x 50 words each (t 0..99 only)
    uint32_t* sp32 = (uint32_t*)spd;
    uint32_t* tr32 = (uint32_t*)trd;
    const int wbase = b * (TB_LEN / 2);             // word offset within row
    #pragma unroll
    for (int it = 0; it < 25; it++) {
        int idx = it * 256 + tid;                   // 0..6399
        int rowL = idx / 50, e = idx - rowL * 50;
        size_t g = (size_t)(col0 + rowL) * (K_DIM / 2) + wbase + e;
        sp32[g] = s_sp[rowL][e];
        tr32[g] = s_tr[rowL][e];
    }

    if (seg == 3) {
        float2 fo; fo.x = fin0; fo.y = fin1;
        *(float2*)(out + outbase + col) = fo;
    }
}

// ===========================================================================
// Kernel 2: dual fp16 GEMM via mma.sync, 3-stage cp.async pipeline.
// (round-4 structure — at the legacy-HMMA floor; K trimmed to 3200)
// grid = (32 tiles, 4): y&1 = gemm id, y>>1 = k-split. 256 threads, 8 warps
// as 4(m)x2(n), warp tile 32x64, CTA tile 128x128.
// ===========================================================================
#define PITCH       144                  // bytes per smem row (72 halves)
#define A_STAGE     (128 * PITCH)        // 18432
#define STAGE_BYTES (2 * A_STAGE)        // 36864
#define GSMEM_TOTAL (3 * STAGE_BYTES)    // 110592

__global__ void __launch_bounds__(256, 1) gemm_kernel()
{
    extern __shared__ __align__(128) char smem[];
    const uint32_t sb = smem_u32(smem);
    const int tid = threadIdx.x, lane = tid & 31, wid = tid >> 5;
    const int mt = blockIdx.x & 3, ntb = blockIdx.x >> 2;
    const int gsel = blockIdx.y & 1, ks = blockIdx.y >> 1;

    const __half* Ag = gsel ? g_A1 : g_A0;
    const __half* Bg = gsel ? g_B1 : g_B0;
    float* Pg = gsel ? g_P1 : g_P0;
    const size_t kbase = (size_t)ks * K_PART;
    const __half* Arow = Ag + (size_t)(mt * 128) * K_DIM + kbase;
    const __half* Brow = Bg + (size_t)(ntb * 128) * K_DIM + kbase;

    auto load_stage = [&](int c) {
        const uint32_t buf = sb + (c % 3) * STAGE_BYTES;
        #pragma unroll
        for (int it = 0; it < 4; it++) {
            int slot = it * 256 + tid;          // 0..1023
            int row = slot >> 3, sub = slot & 7;
            cp_async16(buf + row * PITCH + sub * 16,
                       Arow + (size_t)row * K_DIM + c * CHUNK + sub * 8);
        }
        #pragma unroll
        for (int it = 0; it < 4; it++) {
            int slot = it * 256 + tid;
            int row = slot >> 3, sub = slot & 7;
            cp_async16(buf + A_STAGE + row * PITCH + sub * 16,
                       Brow + (size_t)row * K_DIM + c * CHUNK + sub * 8);
        }
        CP_COMMIT();
    };

    float acc[2][8][4];
    #pragma unroll
    for (int i = 0; i < 2; i++)
        #pragma unroll
        for (int j = 0; j < 8; j++)
            #pragma unroll
            for (int r = 0; r < 4; r++) acc[i][j][r] = 0.f;

    const int m_base = (wid >> 1) * 32;
    const int n_base = (wid & 1) * 64;
    const uint32_t aoff = (uint32_t)((m_base + (lane & 15)) * PITCH
                                     + (lane >> 4) * 16);
    const uint32_t boff = (uint32_t)(A_STAGE
                          + (n_base + ((lane >> 4) << 3) + (lane & 7)) * PITCH
                          + ((lane >> 3) & 1) * 16);

    load_stage(0);
    load_stage(1);

    for (int c = 0; c < NCHUNKS; c++) {
        CP_WAIT1();
        __syncthreads();
        if (c + 2 < NCHUNKS) load_stage(c + 2); else CP_COMMIT();

        const uint32_t buf = sb + (c % 3) * STAGE_BYTES;
        #pragma unroll
        for (int kk = 0; kk < 4; kk++) {
            const uint32_t k0b = kk * 32;
            uint32_t ra[2][4], rb[4][4];
            #pragma unroll
            for (int mtt = 0; mtt < 2; mtt++)
                ldm_x4(ra[mtt], buf + aoff + mtt * (16 * PITCH) + k0b);
            #pragma unroll
            for (int np = 0; np < 4; np++)
                ldm_x4(rb[np], buf + boff + np * (16 * PITCH) + k0b);
            #pragma unroll
            for (int mtt = 0; mtt < 2; mtt++)
                #pragma unroll
                for (int ntt = 0; ntt < 8; ntt++)
                    mma16816(acc[mtt][ntt], ra[mtt],
                             rb[ntt >> 1][(ntt & 1) * 2],
                             rb[ntt >> 1][(ntt & 1) * 2 + 1]);
        }
    }

    const int gid = lane >> 2, tig = lane & 3;
    #pragma unroll
    for (int mtt = 0; mtt < 2; mtt++) {
        #pragma unroll
        for (int ntt = 0; ntt < 8; ntt++) {
            int m = mt * 128 + m_base + mtt * 16 + gid;
            int n = ntb * 128 + n_base + ntt * 8 + 2 * tig;
            float* d0 = Pg + ((size_t)ks * N_OUTPUT + m) * N_INPUT + n;
            float* d1 = Pg + ((size_t)ks * N_OUTPUT + m + 8) * N_INPUT + n;
            float2 v0; v0.x = acc[mtt][ntt][0]; v0.y = acc[mtt][ntt][1];
            float2 v1; v1.x = acc[mtt][ntt][2]; v1.y = acc[mtt][ntt][3];
            *(float2*)d0 = v0;
            *(float2*)d1 = v1;
        }
    }
}

// ===========================================================================
// Kernel 3: reduce split-K partials + soft bounds -> dw
// ===========================================================================
__global__ void __launch_bounds__(256) reduce_kernel(
    const float* __restrict__ W, float* __restrict__ dw)
{
    const int o = blockIdx.x, t = threadIdx.x;
    const size_t ro = (size_t)o * (N_INPUT / 4) + t;
    float4 s0 = make_float4(0.f, 0.f, 0.f, 0.f);
    float4 s1 = make_float4(0.f, 0.f, 0.f, 0.f);
    #pragma unroll
    for (int p = 0; p < K_SPLIT; p++) {
        float4 a = ((const float4*)g_P0)[(size_t)p * (N_OUTPUT * N_INPUT / 4) + ro];
        float4 b = ((const float4*)g_P1)[(size_t)p * (N_OUTPUT * N_INPUT / 4) + ro];
        s0.x += a.x; s0.y += a.y; s0.z += a.z; s0.w += a.w;
        s1.x += b.x; s1.y += b.y; s1.z += b.z; s1.w += b.w;
    }
    const float c1 = LR_LTP_F / (float)BATCHC;
    const float c2 = LR_LTD_F / (float)BATCHC;
    float4 w4 = ((const float4*)W)[ro];
    float4 r;
    r.x = c1 * (1.f - w4.x) * s0.x + c2 * w4.x * s1.x;
    r.y = c1 * (1.f - w4.y) * s0.y + c2 * w4.y * s1.y;
    r.z = c1 * (1.f - w4.z) * s0.z + c2 * w4.z * s1.z;
    r.w = c1 * (1.f - w4.w) * s0.w + c2 * w4.w * s1.w;
    ((float4*)dw)[ro] = r;
}

// ===========================================================================
extern "C" void kernel_launch(void* const* d_in, const int* in_sizes, int n_in,
                              void* d_out, int out_size)
{
    const float* W        = (const float*)d_in[0];
    const float* pre_s    = (const float*)d_in[1];
    const float* post_s   = (const float*)d_in[2];
    const float* pre_tr0  = (const float*)d_in[3];
    const float* post_tr0 = (const float*)d_in[4];
    float* out = (float*)d_out;
    (void)in_sizes; (void)n_in; (void)out_size;

    cudaFuncSetAttribute(gemm_kernel,
                         cudaFuncAttributeMaxDynamicSharedMemorySize, GSMEM_TOTAL);

    prep_kernel<<<384, 256>>>(pre_s, post_s, pre_tr0, post_tr0, out);
    gemm_kernel<<<dim3(32, 4), 256, GSMEM_TOTAL>>>();
    reduce_kernel<<<N_OUTPUT, 256>>>(W, out);
}